// round 16
// baseline (speedup 1.0000x reference)
#include <cuda_runtime.h>
#include <cuda_fp16.h>
#include <cstdint>

#define DIN 1024
#define HD  128
#define NCHUNK (DIN/32)   // 32

// ---------------- device scratch + preconverted weights --------------------
__device__ __half g_W0T[HD*DIN];
__device__ __half g_W1T[HD*HD];
__device__ __half g_W2T[HD*HD];
__device__ __half g_h[32768*HD];          // normalized h, fp16 (8MB)

// WT[n][k] = fp16(W[k][n])
__global__ void prep_w(const float* __restrict__ W, int K, int which)
{
    __shared__ float t[32][33];
    __half* dst = which==0 ? g_W0T : (which==1 ? g_W1T : g_W2T);
    int bx = blockIdx.x, by = blockIdx.y;
    int tx = threadIdx.x, ty = threadIdx.y;   // (32,8)
    #pragma unroll
    for (int r = 0; r < 32; r += 8)
        t[ty+r][tx] = W[(size_t)(bx*32 + ty + r)*HD + by*32 + tx];
    __syncthreads();
    #pragma unroll
    for (int r = 0; r < 32; r += 8) {
        int n = by*32 + ty + r;
        int k = bx*32 + tx;
        dst[(size_t)n*K + k] = __float2half_rn(t[tx][ty+r]);
    }
}

// ---------------- helpers ---------------------------------------------------
__device__ __forceinline__ uint32_t smem_u32(const void* p) {
    uint32_t a;
    asm("{ .reg .u64 t; cvta.to.shared.u64 t, %1; cvt.u32.u64 %0, t; }" : "=r"(a) : "l"(p));
    return a;
}
__device__ __forceinline__ uint32_t sw64 (uint32_t o) { return o ^ ((o >> 3) & 0x30); }
__device__ __forceinline__ uint32_t sw128(uint32_t o) { return o ^ ((o >> 3) & 0x70); }
__device__ __forceinline__ uint32_t sw256(uint32_t o) { return o ^ ((o >> 4) & 0x70); }

__device__ __forceinline__ void cpasync16(uint32_t dst, const void* src) {
    asm volatile("cp.async.cg.shared.global [%0], [%1], 16;" :: "r"(dst), "l"(src));
}
#define CP_COMMIT()  asm volatile("cp.async.commit_group;" ::: "memory")
#define CP_WAIT0()   asm volatile("cp.async.wait_group 0;"  ::: "memory")
#define CP_WAIT1()   asm volatile("cp.async.wait_group 1;"  ::: "memory")

__device__ __forceinline__ void ldsm4(uint32_t addr, uint32_t* r) {
    asm volatile("ldmatrix.sync.aligned.m8n8.x4.shared.b16 {%0,%1,%2,%3}, [%4];"
        : "=r"(r[0]), "=r"(r[1]), "=r"(r[2]), "=r"(r[3]) : "r"(addr));
}
__device__ __forceinline__ void mma16816(float* c, const uint32_t* a, uint32_t b0, uint32_t b1) {
    asm volatile("mma.sync.aligned.m16n8k16.row.col.f32.f16.f16.f32 "
        "{%0,%1,%2,%3}, {%4,%5,%6,%7}, {%8,%9}, {%0,%1,%2,%3};"
        : "+f"(c[0]), "+f"(c[1]), "+f"(c[2]), "+f"(c[3])
        : "r"(a[0]), "r"(a[1]), "r"(a[2]), "r"(a[3]), "r"(b0), "r"(b1));
}

// ================= KERNEL A: GEMM0 + bias + rmsnorm -> g_h (fp16) ==========
// BM=64, 128 threads, 4 warps (2M x 2N). smem 56KB -> 4 CTAs/SM.
#define STG(s)   ((uint32_t)(s) * 16384u)
#define X_OFF    0
#define B_OFF    8192
#define ASLOT(a) (49152u + (uint32_t)(a) * 4096u)
#define S_PART_A 49152
#define SMEM_A   57344

__global__ __launch_bounds__(128, 4)
void mlp_g0(const float* __restrict__ x, const float* __restrict__ b0)
{
    extern __shared__ char smem[];
    const uint32_t su = smem_u32(smem);
    const int tid  = threadIdx.x;
    const int lane = tid & 31;
    const int wid  = tid >> 5;
    const int wm   = wid & 1;
    const int wn   = wid >> 1;
    const int m0   = blockIdx.x * 64;

    float* part = (float*)(smem + S_PART_A);

    const uint32_t aLane   = (uint32_t)(lane & 15);
    const uint32_t aColSel = (uint32_t)((lane >> 4) * 16);
    const uint32_t bRow    = (uint32_t)((lane & 7) + ((lane >> 4) & 1) * 8);
    const uint32_t bColSel = (uint32_t)(((lane >> 3) & 1) * 16);
    const int colbase = (lane & 3) * 2;
    const int qr = lane >> 2;

    float acc[2][8][4];
    #pragma unroll
    for (int a = 0; a < 2; a++)
        #pragma unroll
        for (int n = 0; n < 8; n++)
            #pragma unroll
            for (int q = 0; q < 4; q++) acc[a][n][q] = 0.f;

    auto cp_chunk = [&](int chunk, int stg) {
        uint32_t sb = STG(stg);
        const float* xb = x + (size_t)m0 * DIN + chunk * 32;
        #pragma unroll
        for (int j = 0; j < 4; j++) {
            int flat = j * 128 + tid;
            int row = flat >> 3, c = flat & 7;
            cpasync16(su + sb + X_OFF + sw128((uint32_t)(row*128 + c*16)),
                      xb + (size_t)row * DIN + c*4);
        }
        const __half* wb = g_W0T + chunk * 32;
        #pragma unroll
        for (int j = 0; j < 4; j++) {
            int flat = j * 128 + tid;
            int row = flat >> 2, g = flat & 3;
            cpasync16(su + sb + B_OFF + sw64((uint32_t)(row*64 + g*16)),
                      wb + (size_t)row * DIN + g*8);
        }
        CP_COMMIT();
    };
    auto convert_x = [&](int stg, int slot) {
        uint32_t xb = STG(stg) + X_OFF;
        uint32_t ab = ASLOT(slot);
        int row = tid >> 1, c = tid & 1;
        uint32_t so = (uint32_t)(row*128 + c*64);
        float4 f0 = *(const float4*)(smem + xb + sw128(so));
        float4 f1 = *(const float4*)(smem + xb + sw128(so + 16));
        float4 f2 = *(const float4*)(smem + xb + sw128(so + 32));
        float4 f3 = *(const float4*)(smem + xb + sw128(so + 48));
        __half2 h0 = __floats2half2_rn(f0.x, f0.y), h1 = __floats2half2_rn(f0.z, f0.w);
        __half2 h2 = __floats2half2_rn(f1.x, f1.y), h3 = __floats2half2_rn(f1.z, f1.w);
        __half2 h4 = __floats2half2_rn(f2.x, f2.y), h5 = __floats2half2_rn(f2.z, f2.w);
        __half2 h6 = __floats2half2_rn(f3.x, f3.y), h7 = __floats2half2_rn(f3.z, f3.w);
        uint4 v0 = { *(uint32_t*)&h0, *(uint32_t*)&h1, *(uint32_t*)&h2, *(uint32_t*)&h3 };
        uint4 v1 = { *(uint32_t*)&h4, *(uint32_t*)&h5, *(uint32_t*)&h6, *(uint32_t*)&h7 };
        *(uint4*)(smem + ab + sw64((uint32_t)(row*64 + c*32)))      = v0;
        *(uint4*)(smem + ab + sw64((uint32_t)(row*64 + c*32 + 16))) = v1;
    };
    auto compute_g0 = [&](int stg, int slot) {
        uint32_t ab = su + ASLOT(slot);
        uint32_t bb = su + STG(stg) + B_OFF;
        #pragma unroll
        for (int ks = 0; ks < 2; ks++) {
            uint32_t af[2][4];
            #pragma unroll
            for (int mi = 0; mi < 2; mi++)
                ldsm4(ab + sw64((uint32_t)(wm*32 + mi*16 + aLane)*64 + (uint32_t)ks*32 + aColSel), af[mi]);
            #pragma unroll
            for (int nn = 0; nn < 4; nn++) {
                uint32_t bf[4];
                ldsm4(bb + sw64((uint32_t)(wn*64 + nn*16 + bRow)*64 + (uint32_t)ks*32 + bColSel), bf);
                #pragma unroll
                for (int mi = 0; mi < 2; mi++) {
                    mma16816(acc[mi][nn*2],   af[mi], bf[0], bf[1]);
                    mma16816(acc[mi][nn*2+1], af[mi], bf[2], bf[3]);
                }
            }
        }
    };

    cp_chunk(0, 0);
    cp_chunk(1, 1);
    CP_WAIT1();
    __syncthreads();
    convert_x(0, 0);

    {
        int sC = 2, sR = 0;
        for (int i = 0; i < NCHUNK; i++) {
            if (i + 2 < NCHUNK) {
                cp_chunk(i + 2, sC);
                if (++sC == 3) sC = 0;
            }
            if (i + 1 < NCHUNK) {
                if (i + 2 < NCHUNK) CP_WAIT1(); else CP_WAIT0();
                __syncthreads();
                int st = sR + 1; if (st == 3) st = 0;
                convert_x(st, (i + 1) & 1);
            }
            compute_g0(sR, i & 1);
            if (++sR == 3) sR = 0;
            __syncthreads();
        }
    }

    // ---- bias + rmsnorm; store h fp16 to gmem -------------------------------
    float ssp[4] = {0.f, 0.f, 0.f, 0.f};
    #pragma unroll
    for (int mi = 0; mi < 2; mi++)
        #pragma unroll
        for (int n8 = 0; n8 < 8; n8++) {
            float2 bv = *(const float2*)&b0[wn*64 + n8*8 + colbase];
            float* c = acc[mi][n8];
            c[0] += bv.x; c[1] += bv.y; c[2] += bv.x; c[3] += bv.y;
            ssp[mi*2]   = fmaf(c[0], c[0], fmaf(c[1], c[1], ssp[mi*2]));
            ssp[mi*2+1] = fmaf(c[2], c[2], fmaf(c[3], c[3], ssp[mi*2+1]));
        }
    #pragma unroll
    for (int i = 0; i < 4; i++) {
        ssp[i] += __shfl_xor_sync(0xffffffffu, ssp[i], 1);
        ssp[i] += __shfl_xor_sync(0xffffffffu, ssp[i], 2);
    }
    if ((lane & 3) == 0) {
        #pragma unroll
        for (int i = 0; i < 4; i++) {
            int r = wm*32 + (i >> 1)*16 + (i & 1)*8 + qr;
            part[wn*64 + r] = ssp[i];
        }
    }
    __syncthreads();
    #pragma unroll
    for (int i = 0; i < 4; i++) {
        int r = wm*32 + (i >> 1)*16 + (i & 1)*8 + qr;
        float ss = part[r] + part[64 + r];
        float sc = rsqrtf(ss * (1.f/128.f) + 1e-6f);
        int mi = i >> 1, half = i & 1;
        __half* hrow = g_h + (size_t)(m0 + r) * HD;
        #pragma unroll
        for (int n8 = 0; n8 < 8; n8++) {
            float v0 = acc[mi][n8][half*2]     * sc;
            float v1 = acc[mi][n8][half*2 + 1] * sc;
            __half2 h2 = __floats2half2_rn(v0, v1);
            *(__half2*)(hrow + wn*64 + n8*8 + colbase) = h2;
        }
    }
}

// ================= KERNEL B: GEMM1 + GEMM2 + epilogues =====================
// BM=128, 256 threads, 8 warps (4M x 2N). smem 96KB -> 2 CTAs/SM.
#define BH_OFF  0u          // h tile: 128 rows x 256B (sw256), 32KB
#define BW1     32768u      // W1: 128 n-rows x 256B (sw256), 32KB
#define BW2     65536u      // W2: 128 n-rows x 256B (sw256), 32KB
#define SMEM_B  98304

__global__ __launch_bounds__(256, 2)
void mlp_g12(const float* __restrict__ b1,
             const float* __restrict__ b2,
             float* __restrict__ out)
{
    extern __shared__ char smem[];
    const uint32_t su = smem_u32(smem);
    const int tid  = threadIdx.x;
    const int lane = tid & 31;
    const int wid  = tid >> 5;       // 8 warps: 4 in M x 2 in N
    const int wm   = wid & 3;        // rows wm*32..+32
    const int wn   = wid >> 2;       // cols wn*64..+64
    const int m0   = blockIdx.x * 128;

    const uint32_t aLane   = (uint32_t)(lane & 15);
    const uint32_t aColSel = (uint32_t)((lane >> 4) * 16);
    const uint32_t bRow    = (uint32_t)((lane & 7) + ((lane >> 4) & 1) * 8);
    const uint32_t bColSel = (uint32_t)(((lane >> 3) & 1) * 16);
    const int colbase = (lane & 3) * 2;
    const int qr = lane >> 2;

    // ---- load h + W1 + W2 (3 commit groups) --------------------------------
    {
        const __half* hb = g_h + (size_t)m0 * HD;
        #pragma unroll
        for (int j = 0; j < 8; j++) {
            int flat = j * 256 + tid;        // 0..2047
            int row = flat >> 4, g = flat & 15;
            cpasync16(su + BH_OFF + sw256((uint32_t)(row*256 + g*16)),
                      hb + (size_t)row * HD + g*8);
        }
        CP_COMMIT();
        #pragma unroll
        for (int j = 0; j < 8; j++) {
            int flat = j * 256 + tid;
            int row = flat >> 4, g = flat & 15;
            cpasync16(su + BW1 + sw256((uint32_t)(row*256 + g*16)),
                      g_W1T + (size_t)row * HD + g*8);
        }
        CP_COMMIT();
        #pragma unroll
        for (int j = 0; j < 8; j++) {
            int flat = j * 256 + tid;
            int row = flat >> 4, g = flat & 15;
            cpasync16(su + BW2 + sw256((uint32_t)(row*256 + g*16)),
                      g_W2T + (size_t)row * HD + g*8);
        }
        CP_COMMIT();
    }

    float acc[2][8][4];
    auto zero_acc = [&]() {
        #pragma unroll
        for (int a = 0; a < 2; a++)
            #pragma unroll
            for (int n = 0; n < 8; n++)
                #pragma unroll
                for (int q = 0; q < 4; q++) acc[a][n][q] = 0.f;
    };

    // GEMM: A = h tile (256B rows), B = W buffer (256B rows), k=128
    auto compute = [&](uint32_t wbase) {
        #pragma unroll
        for (int ks = 0; ks < 8; ks++) {
            uint32_t af[2][4];
            #pragma unroll
            for (int mi = 0; mi < 2; mi++)
                ldsm4(su + BH_OFF + sw256((uint32_t)(wm*32 + mi*16 + aLane)*256 + (uint32_t)ks*32 + aColSel), af[mi]);
            #pragma unroll
            for (int nn = 0; nn < 4; nn++) {
                uint32_t bf[4];
                ldsm4(su + wbase + sw256((uint32_t)(wn*64 + nn*16 + bRow)*256 + (uint32_t)ks*32 + bColSel), bf);
                #pragma unroll
                for (int mi = 0; mi < 2; mi++) {
                    mma16816(acc[mi][nn*2],   af[mi], bf[0], bf[1]);
                    mma16816(acc[mi][nn*2+1], af[mi], bf[2], bf[3]);
                }
            }
        }
    };

    CP_WAIT1();                // h + W1 in (W2 may still fly)
    __syncthreads();

    // ---- GEMM1: z = h @ W1 --------------------------------------------------
    zero_acc();
    compute(BW1);
    __syncthreads();           // all warps done reading h

    // ---- epilogue 1: sigmoid + residual; rewrite h in smem ------------------
    #pragma unroll
    for (int mi = 0; mi < 2; mi++)
        #pragma unroll
        for (int half = 0; half < 2; half++) {
            int r = wm*32 + mi*16 + half*8 + qr;
            #pragma unroll
            for (int n8 = 0; n8 < 8; n8++) {
                int col = wn*64 + n8*8 + colbase;
                float2 bv = *(const float2*)&b1[col];
                uint32_t off = sw256((uint32_t)(r*256 + col*2));
                uint32_t hu = *(uint32_t*)(smem + BH_OFF + off);
                __half2 hb = *(__half2*)&hu;
                float r0 = __low2float(hb), r1 = __high2float(hb);
                float v0 = 1.f / (1.f + __expf(-(acc[mi][n8][half*2]     + bv.x))) + r0;
                float v1 = 1.f / (1.f + __expf(-(acc[mi][n8][half*2 + 1] + bv.y))) + r1;
                __half2 h2 = __floats2half2_rn(v0, v1);
                *(uint32_t*)(smem + BH_OFF + off) = *(uint32_t*)&h2;
            }
        }
    CP_WAIT0();                // W2 in
    __syncthreads();           // h1 + W2 visible

    // ---- GEMM2: z = h1 @ W2 -------------------------------------------------
    zero_acc();
    compute(BW2);

    // ---- epilogue 2: relu + residual; store ---------------------------------
    #pragma unroll
    for (int mi = 0; mi < 2; mi++)
        #pragma unroll
        for (int half = 0; half < 2; half++) {
            int r = wm*32 + mi*16 + half*8 + qr;
            float* orow = out + (size_t)(m0 + r) * HD;
            #pragma unroll
            for (int n8 = 0; n8 < 8; n8++) {
                int col = wn*64 + n8*8 + colbase;
                float2 bv = *(const float2*)&b2[col];
                uint32_t hu = *(uint32_t*)(smem + BH_OFF + sw256((uint32_t)(r*256 + col*2)));
                __half2 hb = *(__half2*)&hu;
                float2 o;
                o.x = fmaxf(acc[mi][n8][half*2]     + bv.x, 0.f) + __low2float(hb);
                o.y = fmaxf(acc[mi][n8][half*2 + 1] + bv.y, 0.f) + __high2float(hb);
                *(float2*)(orow + col) = o;
            }
        }
}

// ---------------- launch ----------------------------------------------------
extern "C" void kernel_launch(void* const* d_in, const int* in_sizes, int n_in,
                              void* d_out, int out_size)
{
    const float* x  = (const float*)d_in[0];
    const float* W0 = (const float*)d_in[1];
    const float* b0 = (const float*)d_in[2];
    const float* W1 = (const float*)d_in[3];
    const float* b1 = (const float*)d_in[4];
    const float* W2 = (const float*)d_in[5];
    const float* b2 = (const float*)d_in[6];
    float* out = (float*)d_out;

    const int M = in_sizes[0] / DIN;   // 32768

    prep_w<<<dim3(DIN/32, HD/32), dim3(32, 8)>>>(W0, DIN, 0);
    prep_w<<<dim3(HD/32,  HD/32), dim3(32, 8)>>>(W1, HD, 1);
    prep_w<<<dim3(HD/32,  HD/32), dim3(32, 8)>>>(W2, HD, 2);

    cudaFuncSetAttribute(mlp_g0,
                         cudaFuncAttributeMaxDynamicSharedMemorySize, SMEM_A);
    cudaFuncSetAttribute(mlp_g12,
                         cudaFuncAttributeMaxDynamicSharedMemorySize, SMEM_B);

    mlp_g0 <<<M / 64, 128, SMEM_A>>>(x, b0);
    mlp_g12<<<M / 128, 256, SMEM_B>>>(b1, b2, out);
}

// round 17
// speedup vs baseline: 1.0255x; 1.0255x over previous
#include <cuda_runtime.h>
#include <cuda_fp16.h>
#include <cstdint>

#define DIN 1024
#define HD  128
#define NCHUNK (DIN/32)   // 32

// ---------------- device scratch + preconverted weights --------------------
__device__ __half g_W0T[HD*DIN];
__device__ __half g_W1T[HD*HD];
__device__ __half g_W2T[HD*HD];
__device__ __half g_h[32768*HD];          // normalized h, fp16 (8MB)

// WT[n][k] = fp16(W[k][n])
__global__ void prep_w(const float* __restrict__ W, int K, int which)
{
    __shared__ float t[32][33];
    __half* dst = which==0 ? g_W0T : (which==1 ? g_W1T : g_W2T);
    int bx = blockIdx.x, by = blockIdx.y;
    int tx = threadIdx.x, ty = threadIdx.y;   // (32,8)
    #pragma unroll
    for (int r = 0; r < 32; r += 8)
        t[ty+r][tx] = W[(size_t)(bx*32 + ty + r)*HD + by*32 + tx];
    __syncthreads();
    #pragma unroll
    for (int r = 0; r < 32; r += 8) {
        int n = by*32 + ty + r;
        int k = bx*32 + tx;
        dst[(size_t)n*K + k] = __float2half_rn(t[tx][ty+r]);
    }
}

// ---------------- helpers ---------------------------------------------------
__device__ __forceinline__ uint32_t smem_u32(const void* p) {
    uint32_t a;
    asm("{ .reg .u64 t; cvta.to.shared.u64 t, %1; cvt.u32.u64 %0, t; }" : "=r"(a) : "l"(p));
    return a;
}
__device__ __forceinline__ uint32_t sw64 (uint32_t o) { return o ^ ((o >> 3) & 0x30); }
__device__ __forceinline__ uint32_t sw128(uint32_t o) { return o ^ ((o >> 3) & 0x70); }
__device__ __forceinline__ uint32_t sw256(uint32_t o) { return o ^ ((o >> 4) & 0x70); }

__device__ __forceinline__ void cpasync16(uint32_t dst, const void* src) {
    asm volatile("cp.async.cg.shared.global [%0], [%1], 16;" :: "r"(dst), "l"(src));
}
#define CP_COMMIT()  asm volatile("cp.async.commit_group;" ::: "memory")
#define CP_WAIT0()   asm volatile("cp.async.wait_group 0;"  ::: "memory")
#define CP_WAIT1()   asm volatile("cp.async.wait_group 1;"  ::: "memory")

__device__ __forceinline__ void ldsm4(uint32_t addr, uint32_t* r) {
    asm volatile("ldmatrix.sync.aligned.m8n8.x4.shared.b16 {%0,%1,%2,%3}, [%4];"
        : "=r"(r[0]), "=r"(r[1]), "=r"(r[2]), "=r"(r[3]) : "r"(addr));
}
__device__ __forceinline__ void mma16816(float* c, const uint32_t* a, uint32_t b0, uint32_t b1) {
    asm volatile("mma.sync.aligned.m16n8k16.row.col.f32.f16.f16.f32 "
        "{%0,%1,%2,%3}, {%4,%5,%6,%7}, {%8,%9}, {%0,%1,%2,%3};"
        : "+f"(c[0]), "+f"(c[1]), "+f"(c[2]), "+f"(c[3])
        : "r"(a[0]), "r"(a[1]), "r"(a[2]), "r"(a[3]), "r"(b0), "r"(b1));
}

// ================= KERNEL A: GEMM0 + bias + rmsnorm -> g_h (fp16) ==========
// BM=64, 128 threads, 4 warps (2M x 2N). smem 56KB -> 4 CTAs/SM. (unchanged)
#define STG(s)   ((uint32_t)(s) * 16384u)
#define X_OFF    0
#define B_OFF    8192
#define ASLOT(a) (49152u + (uint32_t)(a) * 4096u)
#define S_PART_A 49152
#define SMEM_A   57344

__global__ __launch_bounds__(128, 4)
void mlp_g0(const float* __restrict__ x, const float* __restrict__ b0)
{
    extern __shared__ char smem[];
    const uint32_t su = smem_u32(smem);
    const int tid  = threadIdx.x;
    const int lane = tid & 31;
    const int wid  = tid >> 5;
    const int wm   = wid & 1;
    const int wn   = wid >> 1;
    const int m0   = blockIdx.x * 64;

    float* part = (float*)(smem + S_PART_A);

    const uint32_t aLane   = (uint32_t)(lane & 15);
    const uint32_t aColSel = (uint32_t)((lane >> 4) * 16);
    const uint32_t bRow    = (uint32_t)((lane & 7) + ((lane >> 4) & 1) * 8);
    const uint32_t bColSel = (uint32_t)(((lane >> 3) & 1) * 16);
    const int colbase = (lane & 3) * 2;
    const int qr = lane >> 2;

    float acc[2][8][4];
    #pragma unroll
    for (int a = 0; a < 2; a++)
        #pragma unroll
        for (int n = 0; n < 8; n++)
            #pragma unroll
            for (int q = 0; q < 4; q++) acc[a][n][q] = 0.f;

    auto cp_chunk = [&](int chunk, int stg) {
        uint32_t sb = STG(stg);
        const float* xb = x + (size_t)m0 * DIN + chunk * 32;
        #pragma unroll
        for (int j = 0; j < 4; j++) {
            int flat = j * 128 + tid;
            int row = flat >> 3, c = flat & 7;
            cpasync16(su + sb + X_OFF + sw128((uint32_t)(row*128 + c*16)),
                      xb + (size_t)row * DIN + c*4);
        }
        const __half* wb = g_W0T + chunk * 32;
        #pragma unroll
        for (int j = 0; j < 4; j++) {
            int flat = j * 128 + tid;
            int row = flat >> 2, g = flat & 3;
            cpasync16(su + sb + B_OFF + sw64((uint32_t)(row*64 + g*16)),
                      wb + (size_t)row * DIN + g*8);
        }
        CP_COMMIT();
    };
    auto convert_x = [&](int stg, int slot) {
        uint32_t xb = STG(stg) + X_OFF;
        uint32_t ab = ASLOT(slot);
        int row = tid >> 1, c = tid & 1;
        uint32_t so = (uint32_t)(row*128 + c*64);
        float4 f0 = *(const float4*)(smem + xb + sw128(so));
        float4 f1 = *(const float4*)(smem + xb + sw128(so + 16));
        float4 f2 = *(const float4*)(smem + xb + sw128(so + 32));
        float4 f3 = *(const float4*)(smem + xb + sw128(so + 48));
        __half2 h0 = __floats2half2_rn(f0.x, f0.y), h1 = __floats2half2_rn(f0.z, f0.w);
        __half2 h2 = __floats2half2_rn(f1.x, f1.y), h3 = __floats2half2_rn(f1.z, f1.w);
        __half2 h4 = __floats2half2_rn(f2.x, f2.y), h5 = __floats2half2_rn(f2.z, f2.w);
        __half2 h6 = __floats2half2_rn(f3.x, f3.y), h7 = __floats2half2_rn(f3.z, f3.w);
        uint4 v0 = { *(uint32_t*)&h0, *(uint32_t*)&h1, *(uint32_t*)&h2, *(uint32_t*)&h3 };
        uint4 v1 = { *(uint32_t*)&h4, *(uint32_t*)&h5, *(uint32_t*)&h6, *(uint32_t*)&h7 };
        *(uint4*)(smem + ab + sw64((uint32_t)(row*64 + c*32)))      = v0;
        *(uint4*)(smem + ab + sw64((uint32_t)(row*64 + c*32 + 16))) = v1;
    };
    auto compute_g0 = [&](int stg, int slot) {
        uint32_t ab = su + ASLOT(slot);
        uint32_t bb = su + STG(stg) + B_OFF;
        #pragma unroll
        for (int ks = 0; ks < 2; ks++) {
            uint32_t af[2][4];
            #pragma unroll
            for (int mi = 0; mi < 2; mi++)
                ldsm4(ab + sw64((uint32_t)(wm*32 + mi*16 + aLane)*64 + (uint32_t)ks*32 + aColSel), af[mi]);
            #pragma unroll
            for (int nn = 0; nn < 4; nn++) {
                uint32_t bf[4];
                ldsm4(bb + sw64((uint32_t)(wn*64 + nn*16 + bRow)*64 + (uint32_t)ks*32 + bColSel), bf);
                #pragma unroll
                for (int mi = 0; mi < 2; mi++) {
                    mma16816(acc[mi][nn*2],   af[mi], bf[0], bf[1]);
                    mma16816(acc[mi][nn*2+1], af[mi], bf[2], bf[3]);
                }
            }
        }
    };

    cp_chunk(0, 0);
    cp_chunk(1, 1);
    CP_WAIT1();
    __syncthreads();
    convert_x(0, 0);

    {
        int sC = 2, sR = 0;
        for (int i = 0; i < NCHUNK; i++) {
            if (i + 2 < NCHUNK) {
                cp_chunk(i + 2, sC);
                if (++sC == 3) sC = 0;
            }
            if (i + 1 < NCHUNK) {
                if (i + 2 < NCHUNK) CP_WAIT1(); else CP_WAIT0();
                __syncthreads();
                int st = sR + 1; if (st == 3) st = 0;
                convert_x(st, (i + 1) & 1);
            }
            compute_g0(sR, i & 1);
            if (++sR == 3) sR = 0;
            __syncthreads();
        }
    }

    // ---- bias + rmsnorm; store h fp16 to gmem -------------------------------
    float ssp[4] = {0.f, 0.f, 0.f, 0.f};
    #pragma unroll
    for (int mi = 0; mi < 2; mi++)
        #pragma unroll
        for (int n8 = 0; n8 < 8; n8++) {
            float2 bv = *(const float2*)&b0[wn*64 + n8*8 + colbase];
            float* c = acc[mi][n8];
            c[0] += bv.x; c[1] += bv.y; c[2] += bv.x; c[3] += bv.y;
            ssp[mi*2]   = fmaf(c[0], c[0], fmaf(c[1], c[1], ssp[mi*2]));
            ssp[mi*2+1] = fmaf(c[2], c[2], fmaf(c[3], c[3], ssp[mi*2+1]));
        }
    #pragma unroll
    for (int i = 0; i < 4; i++) {
        ssp[i] += __shfl_xor_sync(0xffffffffu, ssp[i], 1);
        ssp[i] += __shfl_xor_sync(0xffffffffu, ssp[i], 2);
    }
    if ((lane & 3) == 0) {
        #pragma unroll
        for (int i = 0; i < 4; i++) {
            int r = wm*32 + (i >> 1)*16 + (i & 1)*8 + qr;
            part[wn*64 + r] = ssp[i];
        }
    }
    __syncthreads();
    #pragma unroll
    for (int i = 0; i < 4; i++) {
        int r = wm*32 + (i >> 1)*16 + (i & 1)*8 + qr;
        float ss = part[r] + part[64 + r];
        float sc = rsqrtf(ss * (1.f/128.f) + 1e-6f);
        int mi = i >> 1, half = i & 1;
        __half* hrow = g_h + (size_t)(m0 + r) * HD;
        #pragma unroll
        for (int n8 = 0; n8 < 8; n8++) {
            float v0 = acc[mi][n8][half*2]     * sc;
            float v1 = acc[mi][n8][half*2 + 1] * sc;
            __half2 h2 = __floats2half2_rn(v0, v1);
            *(__half2*)(hrow + wn*64 + n8*8 + colbase) = h2;
        }
    }
}

// ================= KERNEL B: GEMM1 + GEMM2 + epilogues (v17) ===============
// BM=64, 128 threads, 4 warps (2M x 2N). smem 48KB -> 4 CTAs/SM, grid 512 =
// single wave. W1/W2 streamed in k-halves through a 2x16KB double buffer.
#define BH_OFF  0u          // h tile: 64 rows x 256B (sw256), 16KB
#define WQ0b    16384u      // W half buffer 0: 128 n-rows x 128B (sw128)
#define WQ1b    32768u      // W half buffer 1
#define SMEM_B  49152

__global__ __launch_bounds__(128, 4)
void mlp_g12(const float* __restrict__ b1,
             const float* __restrict__ b2,
             float* __restrict__ out)
{
    extern __shared__ char smem[];
    const uint32_t su = smem_u32(smem);
    const int tid  = threadIdx.x;
    const int lane = tid & 31;
    const int wid  = tid >> 5;       // 4 warps: 2 in M x 2 in N
    const int wm   = wid & 1;        // rows wm*32..+32
    const int wn   = wid >> 1;       // cols wn*64..+64
    const int m0   = blockIdx.x * 64;

    const uint32_t aLane   = (uint32_t)(lane & 15);
    const uint32_t aColSel = (uint32_t)((lane >> 4) * 16);
    const uint32_t bRow    = (uint32_t)((lane & 7) + ((lane >> 4) & 1) * 8);
    const uint32_t bColSel = (uint32_t)(((lane >> 3) & 1) * 16);
    const int colbase = (lane & 3) * 2;
    const int qr = lane >> 2;

    // ---- async loaders ------------------------------------------------------
    auto cp_h = [&]() {
        const __half* hb = g_h + (size_t)m0 * HD;
        #pragma unroll
        for (int j = 0; j < 8; j++) {
            int flat = j * 128 + tid;        // 0..1023
            int row = flat >> 4, g = flat & 15;
            cpasync16(su + BH_OFF + sw256((uint32_t)(row*256 + g*16)),
                      hb + (size_t)row * HD + g*8);
        }
        CP_COMMIT();
    };
    auto cp_Whalf = [&](const __half* src, int half, uint32_t dstb) {
        #pragma unroll
        for (int j = 0; j < 8; j++) {
            int flat = j * 128 + tid;        // 0..1023
            int row = flat >> 3, g = flat & 7;
            cpasync16(su + dstb + sw128((uint32_t)(row*128 + g*16)),
                      src + (size_t)row * HD + half*64 + g*8);
        }
        CP_COMMIT();
    };

    float acc[2][8][4];
    auto zero_acc = [&]() {
        #pragma unroll
        for (int a = 0; a < 2; a++)
            #pragma unroll
            for (int n = 0; n < 8; n++)
                #pragma unroll
                for (int q = 0; q < 4; q++) acc[a][n][q] = 0.f;
    };

    // GEMM: A = h tile (256B rows) k-offset kbyte, B = W half buffer (128B rows)
    auto compute = [&](uint32_t wbase, uint32_t kbyte) {
        #pragma unroll
        for (int ks = 0; ks < 4; ks++) {
            uint32_t af[2][4];
            #pragma unroll
            for (int mi = 0; mi < 2; mi++)
                ldsm4(su + BH_OFF + sw256((uint32_t)(wm*32 + mi*16 + aLane)*256 + kbyte + (uint32_t)ks*32 + aColSel), af[mi]);
            #pragma unroll
            for (int nn = 0; nn < 4; nn++) {
                uint32_t bf[4];
                ldsm4(su + wbase + sw128((uint32_t)(wn*64 + nn*16 + bRow)*128 + (uint32_t)ks*32 + bColSel), bf);
                #pragma unroll
                for (int mi = 0; mi < 2; mi++) {
                    mma16816(acc[mi][nn*2],   af[mi], bf[0], bf[1]);
                    mma16816(acc[mi][nn*2+1], af[mi], bf[2], bf[3]);
                }
            }
        }
    };

    // ---- prologue: h + W1 halves in flight ---------------------------------
    cp_h();                       // group: h
    cp_Whalf(g_W1T, 0, WQ0b);     // group: W1 half0
    cp_Whalf(g_W1T, 1, WQ1b);     // group: W1 half1
    CP_WAIT1();                   // h + W1h0 done (W1h1 may fly)
    __syncthreads();

    // ---- GEMM1: z = h @ W1 (k-halves) --------------------------------------
    zero_acc();
    compute(WQ0b, 0);
    __syncthreads();              // WQ0 free
    cp_Whalf(g_W2T, 0, WQ0b);     // group: W2 half0
    CP_WAIT1();                   // W1 half1 in
    __syncthreads();
    compute(WQ1b, 128);
    __syncthreads();              // WQ1 free
    cp_Whalf(g_W2T, 1, WQ1b);     // group: W2 half1

    // ---- epilogue 1: sigmoid + residual; rewrite h in smem ------------------
    #pragma unroll
    for (int mi = 0; mi < 2; mi++)
        #pragma unroll
        for (int half = 0; half < 2; half++) {
            int r = wm*32 + mi*16 + half*8 + qr;
            #pragma unroll
            for (int n8 = 0; n8 < 8; n8++) {
                int col = wn*64 + n8*8 + colbase;
                float2 bv = *(const float2*)&b1[col];
                uint32_t off = sw256((uint32_t)(r*256 + col*2));
                uint32_t hu = *(uint32_t*)(smem + BH_OFF + off);
                __half2 hb = *(__half2*)&hu;
                float r0 = __low2float(hb), r1 = __high2float(hb);
                float v0 = 1.f / (1.f + __expf(-(acc[mi][n8][half*2]     + bv.x))) + r0;
                float v1 = 1.f / (1.f + __expf(-(acc[mi][n8][half*2 + 1] + bv.y))) + r1;
                __half2 h2 = __floats2half2_rn(v0, v1);
                *(uint32_t*)(smem + BH_OFF + off) = *(uint32_t*)&h2;
            }
        }
    CP_WAIT1();                   // W2 half0 in
    __syncthreads();              // h1 + WQ0 visible

    // ---- GEMM2: z = h1 @ W2 (k-halves) --------------------------------------
    zero_acc();
    compute(WQ0b, 0);
    CP_WAIT0();                   // W2 half1 in
    __syncthreads();
    compute(WQ1b, 128);

    // ---- epilogue 2: relu + residual; store ---------------------------------
    #pragma unroll
    for (int mi = 0; mi < 2; mi++)
        #pragma unroll
        for (int half = 0; half < 2; half++) {
            int r = wm*32 + mi*16 + half*8 + qr;
            float* orow = out + (size_t)(m0 + r) * HD;
            #pragma unroll
            for (int n8 = 0; n8 < 8; n8++) {
                int col = wn*64 + n8*8 + colbase;
                float2 bv = *(const float2*)&b2[col];
                uint32_t hu = *(uint32_t*)(smem + BH_OFF + sw256((uint32_t)(r*256 + col*2)));
                __half2 hb = *(__half2*)&hu;
                float2 o;
                o.x = fmaxf(acc[mi][n8][half*2]     + bv.x, 0.f) + __low2float(hb);
                o.y = fmaxf(acc[mi][n8][half*2 + 1] + bv.y, 0.f) + __high2float(hb);
                *(float2*)(orow + col) = o;
            }
        }
}

// ---------------- launch ----------------------------------------------------
extern "C" void kernel_launch(void* const* d_in, const int* in_sizes, int n_in,
                              void* d_out, int out_size)
{
    const float* x  = (const float*)d_in[0];
    const float* W0 = (const float*)d_in[1];
    const float* b0 = (const float*)d_in[2];
    const float* W1 = (const float*)d_in[3];
    const float* b1 = (const float*)d_in[4];
    const float* W2 = (const float*)d_in[5];
    const float* b2 = (const float*)d_in[6];
    float* out = (float*)d_out;

    const int M = in_sizes[0] / DIN;   // 32768

    prep_w<<<dim3(DIN/32, HD/32), dim3(32, 8)>>>(W0, DIN, 0);
    prep_w<<<dim3(HD/32,  HD/32), dim3(32, 8)>>>(W1, HD, 1);
    prep_w<<<dim3(HD/32,  HD/32), dim3(32, 8)>>>(W2, HD, 2);

    cudaFuncSetAttribute(mlp_g0,
                         cudaFuncAttributeMaxDynamicSharedMemorySize, SMEM_A);
    cudaFuncSetAttribute(mlp_g12,
                         cudaFuncAttributeMaxDynamicSharedMemorySize, SMEM_B);

    mlp_g0 <<<M / 64, 128, SMEM_A>>>(x, b0);
    mlp_g12<<<M / 64, 128, SMEM_B>>>(b1, b2, out);
}